// round 5
// baseline (speedup 1.0000x reference)
#include <cuda_runtime.h>
#include <math.h>

// Q,K,V,O : [4,16,4096,64] fp32.
// out = rmsnorm( V * (1 + silu( rmsnorm(cumsum_s(silu(V)*V)) / (||Q||+||K||+1+2e-8) )) )
//
// Decoupled-lookback scan, 256 threads, CHUNK=64.
// SAME thread mapping in both phases: thread (g,q) owns rows 4g..4g+3,
// channels 4q..4q+3. V and local cumsums stay in registers; D-reductions are
// half-warp shfl_xor. Phase B is barrier-free and SMEM-free.

#define BH      64
#define SEQ     4096
#define DIM     64
#define CHUNK   64
#define NCHUNK  64
#define NGRP    16
#define NBLK    (BH * NCHUNK)   // 4096

__device__ float g_agg[NBLK * DIM];
__device__ int   g_flag[NBLK];

__device__ __forceinline__ float sigf(float x) {
    return __fdividef(1.0f, 1.0f + __expf(-x));
}
__device__ __forceinline__ float4 add4(float4 a, float4 b) {
    return make_float4(a.x + b.x, a.y + b.y, a.z + b.z, a.w + b.w);
}
__device__ __forceinline__ float4 sw4(float4 v) {
    return make_float4(v.x * v.x * sigf(v.x), v.y * v.y * sigf(v.y),
                       v.z * v.z * sigf(v.z), v.w * v.w * sigf(v.w));
}
__device__ __forceinline__ float dot4(float4 a) {
    return a.x * a.x + a.y * a.y + a.z * a.z + a.w * a.w;
}
__device__ __forceinline__ int ld_acq(const int* p) {
    int v;
    asm volatile("ld.global.acquire.gpu.b32 %0, [%1];" : "=r"(v) : "l"(p) : "memory");
    return v;
}

extern "C" __global__ void __launch_bounds__(256, 4)
k_fused(const float* __restrict__ Q, const float* __restrict__ K,
        const float* __restrict__ V, float* __restrict__ O)
{
    __shared__ float  gs[NGRP][68];     // group sums (transposed for scan)
    __shared__ float  offs[NGRP][68];   // exclusive cross-group prefixes
    __shared__ float4 basev[16];        // chunk base (from lookback)
    __shared__ float  pre[4][DIM];      // lookback partials

    const int blk = blockIdx.x;
    const int bh  = blk >> 6;
    const int ch  = blk & 63;
    const size_t cbase = ((size_t)bh * SEQ + (size_t)ch * CHUNK) * DIM;
    const int tid  = threadIdx.x;
    const int lane = tid & 31;
    const int w    = tid >> 5;
    const int q    = tid & 15;          // d-quad (channels 4q..4q+3)
    const int g    = tid >> 4;          // row group (rows 4g..4g+3)

    // ---------------- Phase A: load V, local cumsum (registers) ----------------
    const float* vp = V + cbase + (size_t)(g * 4) * DIM + q * 4;
    float4 v0 = *(const float4*)(vp);
    float4 v1 = *(const float4*)(vp + DIM);
    float4 v2 = *(const float4*)(vp + 2 * DIM);
    float4 v3 = *(const float4*)(vp + 3 * DIM);

    float4 a0 = sw4(v0);
    float4 a1 = add4(a0, sw4(v1));
    float4 a2 = add4(a1, sw4(v2));
    float4 a3 = add4(a2, sw4(v3));
    *(float4*)&gs[g][q * 4] = a3;
    __syncthreads();

    // ---------------- Warp-shuffle scan over 16 group sums ----------------
    {
        const int seg = lane >> 4;
        const int sl  = lane & 15;          // group index in scan
        const int qq  = w * 2 + seg;        // d-quad handled by this scan lane

        float4 incl = *(const float4*)&gs[sl][qq * 4];
        #pragma unroll
        for (int st = 1; st < 16; st <<= 1) {
            float4 t;
            t.x = __shfl_up_sync(0xFFFFFFFFu, incl.x, st);
            t.y = __shfl_up_sync(0xFFFFFFFFu, incl.y, st);
            t.z = __shfl_up_sync(0xFFFFFFFFu, incl.z, st);
            t.w = __shfl_up_sync(0xFFFFFFFFu, incl.w, st);
            if (sl >= st) incl = add4(incl, t);
        }
        if (sl == 15) {                      // publish chunk aggregate
            *(float4*)(g_agg + (size_t)blk * DIM + qq * 4) = incl;
            __threadfence();
        }
        float4 excl;
        excl.x = __shfl_up_sync(0xFFFFFFFFu, incl.x, 1);
        excl.y = __shfl_up_sync(0xFFFFFFFFu, incl.y, 1);
        excl.z = __shfl_up_sync(0xFFFFFFFFu, incl.z, 1);
        excl.w = __shfl_up_sync(0xFFFFFFFFu, incl.w, 1);
        if (sl == 0) excl = make_float4(0.f, 0.f, 0.f, 0.f);
        *(float4*)&offs[sl][qq * 4] = excl;
    }
    __syncthreads();
    if (tid == 0) atomicExch(&g_flag[blk], 1);

    // ---------------- Lookback ----------------
    if (ch > 0) {
        if (tid < ch) {
            const int* fp = g_flag + bh * NCHUNK + tid;
            while (ld_acq(fp) == 0) __nanosleep(32);
        }
        __syncthreads();
        {
            const int d = tid & 63, j = tid >> 6;
            float p = 0.f;
            for (int cc = j; cc < ch; cc += 4)
                p += __ldcg(g_agg + ((size_t)(bh * NCHUNK + cc)) * DIM + d);
            pre[j][d] = p;
        }
        __syncthreads();
        if (tid < 16) {
            float4 b;
            b.x = pre[0][tid*4+0] + pre[1][tid*4+0] + pre[2][tid*4+0] + pre[3][tid*4+0];
            b.y = pre[0][tid*4+1] + pre[1][tid*4+1] + pre[2][tid*4+1] + pre[3][tid*4+1];
            b.z = pre[0][tid*4+2] + pre[1][tid*4+2] + pre[2][tid*4+2] + pre[3][tid*4+2];
            b.w = pre[0][tid*4+3] + pre[1][tid*4+3] + pre[2][tid*4+3] + pre[3][tid*4+3];
            basev[tid] = b;
        }
    } else {
        if (tid < 16) basev[tid] = make_float4(0.f, 0.f, 0.f, 0.f);
    }
    __syncthreads();

    // Per-thread total offset: chunk base + exclusive cross-group prefix
    const float4 off4 = add4(*(const float4*)&offs[g][q * 4], basev[q]);

    // ---------------- Phase B: barrier-free, register-resident ----------------
    // Row j = 4g+j. D-reduction = 16-lane half-warp butterfly (masks 1,2,4,8).
    float4 av[4] = {a0, a1, a2, a3};
    float4 vv[4] = {v0, v1, v2, v3};

    #pragma unroll
    for (int j = 0; j < 4; j++) {
        const size_t roff = cbase + (size_t)(g * 4 + j) * DIM + q * 4;
        float4 q4 = __ldcs((const float4*)(Q + roff));
        float4 k4 = __ldcs((const float4*)(K + roff));

        float4 c4 = add4(av[j], off4);
        float sq = dot4(q4);
        float sk = dot4(k4);
        float sc = dot4(c4);
        #pragma unroll
        for (int m = 8; m; m >>= 1) {
            sq += __shfl_xor_sync(0xFFFFFFFFu, sq, m);
            sk += __shfl_xor_sync(0xFFFFFFFFu, sk, m);
            sc += __shfl_xor_sync(0xFFFFFFFFu, sc, m);
        }

        float rms_c = rsqrtf(sc * (1.0f / DIM) + 1e-5f);
        float r     = sqrtf(sq) + sqrtf(sk) + 1.0f + 2e-8f;
        float scale = __fdividef(rms_c, r);

        float m0 = c4.x * scale, m1 = c4.y * scale;
        float m2 = c4.z * scale, m3 = c4.w * scale;
        float4 v4 = vv[j];
        float o0 = v4.x * (1.0f + m0 * sigf(m0));
        float o1 = v4.y * (1.0f + m1 * sigf(m1));
        float o2 = v4.z * (1.0f + m2 * sigf(m2));
        float o3 = v4.w * (1.0f + m3 * sigf(m3));

        float so = o0 * o0 + o1 * o1 + o2 * o2 + o3 * o3;
        #pragma unroll
        for (int m = 8; m; m >>= 1)
            so += __shfl_xor_sync(0xFFFFFFFFu, so, m);

        float rms_o = rsqrtf(so * (1.0f / DIM) + 1e-5f);
        float4 out = make_float4(o0 * rms_o, o1 * rms_o, o2 * rms_o, o3 * rms_o);
        __stcs((float4*)(O + roff), out);
    }
}

// ---------------------------------------------------------------------------
extern "C" void kernel_launch(void* const* d_in, const int* in_sizes, int n_in,
                              void* d_out, int out_size) {
    const float* Q = (const float*)d_in[0];
    const float* K = (const float*)d_in[1];
    const float* V = (const float*)d_in[2];
    float* O = (float*)d_out;

    void* fp = nullptr;
    cudaGetSymbolAddress(&fp, g_flag);
    cudaMemsetAsync(fp, 0, NBLK * sizeof(int), 0);

    k_fused<<<NBLK, 256>>>(Q, K, V, O);
}